// round 17
// baseline (speedup 1.0000x reference)
#include <cuda_runtime.h>
#include <cuda_fp16.h>

// QLSTM collapsed analytically:
//   quantum_gate(comb, p)[:, k] = prod_{j<=k} cos(p_j) * cos(comb_j)
// Only k < H=4 used; comb[0:4] = x  => gates depend only on x_t.
// Per (b,k): c = f*c + i*g ; h = o*tanh(c); gate args in [-1,1], |c| <= 2.1.
//
// Chassis = round 14 math (best ncu 9.44us). Reshaped for residency:
//   block = 64 thr = 2 warps = (half 0, half 1) of one b-pair; grid = 2048
//   -> up to 16 blocks/SM (single wave, 13.8 blocks/SM avg).
//   Register diet: o-gate cache in half2 (deterministic err <= 5.2e-4 on h),
//   pairwise x loads. FIX vs r16: reload the prefetch pair at it==1 (after
//   consumption), select x by (it & 1).

#define T_STEPS 128
#define BATCH   4096
#define CHUNK   4
#define FULLMASK 0xffffffffu

// sigmoid(2u), |u|<=0.5 : 0.5 + u*q(w), w=u^2; deg-7 economized, err ~3e-7
__device__ __forceinline__ float sig_poly(float u) {
    float w = u * u;
    float q = fmaf(w, fmaf(w, fmaf(w, -0.0215166f,
                                       0.0658124f),
                               -0.1666240f),
                       0.4999997f);
    return fmaf(u, q, 0.5f);
}
// tanh Pade(5,4); err ~4e-8 at |z|<=1, ~3e-5 at |z|<=2.1
__device__ __forceinline__ float tanh_p54(float z) {
    float w = z * z;
    float n = z * fmaf(w, fmaf(w, 1.0f, 105.0f), 945.0f);
    float d =     fmaf(w, fmaf(w, 15.0f, 420.0f), 945.0f);
    return __fdividef(n, d);
}

__global__ void __launch_bounds__(64, 16) qlstm_kernel(
    const float* __restrict__ inp,   // [T, B, 4]
    const float* __restrict__ prm_f, // [8]
    const float* __restrict__ prm_i,
    const float* __restrict__ prm_g,
    const float* __restrict__ prm_o,
    float* __restrict__ out)         // [T*B*4 + B*4 + B*4]
{
    const int tid   = threadIdx.x;
    const int half  = tid >> 5;              // warp 0: t<64, warp 1: t>=64
    const int lane  = tid & 31;
    const int bsub  = lane & 1;
    const int chunk = lane >> 1;             // 0..15
    const int b     = blockIdx.x * 2 + bsub;
    const int t0    = half * 64 + chunk * CHUNK;

    __shared__ float  sC[2][4];              // half-0 total c @t=63 per (bsub,k)
    __shared__ float4 sA[4];                 // AFh, AIh, AG, AOh

    const float4* __restrict__ xin = (const float4*)inp;

    // first pair of inputs (second pair loaded after it==1 consumes xs1)
    float4 xs0 = xin[(t0 + 0) * BATCH + b];
    float4 xs1 = xin[(t0 + 1) * BATCH + b];

    // per-warp redundant param prologue (identical writes are benign)
    if (lane < 16) {
        const int j = lane & 3;
        const float* p = (lane < 8) ? ((lane < 4) ? prm_f : prm_i)
                                    : ((lane < 12) ? prm_g : prm_o);
        float v = __cosf(p[j]);
        float s1 = __shfl_up_sync(0xffffu, v, 1, 4);
        if (j >= 1) v *= s1;
        float s2 = __shfl_up_sync(0xffffu, v, 2, 4);
        if (j >= 2) v *= s2;
        float scale = (lane >= 8 && lane < 12) ? 1.0f : 0.5f;  // AG unscaled
        ((float*)sA)[lane] = scale * v;
    }
    __syncwarp();

    const float4 AF = sA[0], AI = sA[1], AG = sA[2], AO = sA[3];

    // ---- pass 1: cache gates (o compressed to half2), chunk affine map ----
    float Fc[CHUNK][4], Gc[CHUNK][4];
    __half2 OcA[CHUNK], OcB[CHUNK];          // (o0,o1), (o2,o3)
    float cl0 = 0.f, cl1 = 0.f, cl2 = 0.f, cl3 = 0.f;
    float pf0 = 1.f, pf1 = 1.f, pf2 = 1.f, pf3 = 1.f;

#pragma unroll
    for (int it = 0; it < CHUNK; ++it) {
        float4 x = (it & 1) ? xs1 : xs0;     // it0->xs0, it1->xs1, it2->xs0', it3->xs1'
        if (it == 1) {                        // xs0/xs1 both consumed; refill
            xs0 = xin[(t0 + 2) * BATCH + b];
            xs1 = xin[(t0 + 3) * BATCH + b];
        }
        float P0 = __cosf(x.x);
        float P1 = P0 * __cosf(x.y);
        float P2 = P1 * __cosf(x.z);
        float P3 = P2 * __cosf(x.w);

        float f, ig;
        f = sig_poly(AF.x * P0); ig = sig_poly(AI.x * P0) * tanh_p54(AG.x * P0);
        Fc[it][0] = f; Gc[it][0] = ig; cl0 = fmaf(f, cl0, ig); pf0 *= f;

        f = sig_poly(AF.y * P1); ig = sig_poly(AI.y * P1) * tanh_p54(AG.y * P1);
        Fc[it][1] = f; Gc[it][1] = ig; cl1 = fmaf(f, cl1, ig); pf1 *= f;

        f = sig_poly(AF.z * P2); ig = sig_poly(AI.z * P2) * tanh_p54(AG.z * P2);
        Fc[it][2] = f; Gc[it][2] = ig; cl2 = fmaf(f, cl2, ig); pf2 *= f;

        f = sig_poly(AF.w * P3); ig = sig_poly(AI.w * P3) * tanh_p54(AG.w * P3);
        Fc[it][3] = f; Gc[it][3] = ig; cl3 = fmaf(f, cl3, ig); pf3 *= f;

        OcA[it] = __floats2half2_rn(sig_poly(AO.x * P0), sig_poly(AO.y * P1));
        OcB[it] = __floats2half2_rn(sig_poly(AO.z * P2), sig_poly(AO.w * P3));
    }

    // ---- scan over 16 chunks (lanes stride 2, same bsub) ----
    float F0 = pf0, C0 = cl0, F1 = pf1, C1 = cl1;
    float F2 = pf2, C2 = cl2, F3 = pf3, C3 = cl3;
#pragma unroll
    for (int off = 1; off <= 8; off <<= 1) {
        const int ol = off * 2;
        float Fo0 = __shfl_up_sync(FULLMASK, F0, ol), Co0 = __shfl_up_sync(FULLMASK, C0, ol);
        float Fo1 = __shfl_up_sync(FULLMASK, F1, ol), Co1 = __shfl_up_sync(FULLMASK, C1, ol);
        float Fo2 = __shfl_up_sync(FULLMASK, F2, ol), Co2 = __shfl_up_sync(FULLMASK, C2, ol);
        float Fo3 = __shfl_up_sync(FULLMASK, F3, ol), Co3 = __shfl_up_sync(FULLMASK, C3, ol);
        if (chunk >= off) {
            C0 = fmaf(F0, Co0, C0); F0 *= Fo0;
            C1 = fmaf(F1, Co1, C1); F1 *= Fo1;
            C2 = fmaf(F2, Co2, C2); F2 *= Fo2;
            C3 = fmaf(F3, Co3, C3); F3 *= Fo3;
        }
    }

    // half-0 publishes total c at t=63
    if (half == 0 && chunk == 15) {
        sC[bsub][0] = C0;
        sC[bsub][1] = C1;
        sC[bsub][2] = C2;
        sC[bsub][3] = C3;
    }

    // exclusive prefix within this half
    float Fe0 = __shfl_up_sync(FULLMASK, F0, 2), Ce0 = __shfl_up_sync(FULLMASK, C0, 2);
    float Fe1 = __shfl_up_sync(FULLMASK, F1, 2), Ce1 = __shfl_up_sync(FULLMASK, C1, 2);
    float Fe2 = __shfl_up_sync(FULLMASK, F2, 2), Ce2 = __shfl_up_sync(FULLMASK, C2, 2);
    float Fe3 = __shfl_up_sync(FULLMASK, F3, 2), Ce3 = __shfl_up_sync(FULLMASK, C3, 2);
    if (chunk == 0) {
        Fe0 = 1.f; Ce0 = 0.f; Fe1 = 1.f; Ce1 = 0.f;
        Fe2 = 1.f; Ce2 = 0.f; Fe3 = 1.f; Ce3 = 0.f;
    }

    __syncthreads();

    float ch0 = 0.f, ch1 = 0.f, ch2 = 0.f, ch3 = 0.f;
    if (half == 1) {
        ch0 = sC[bsub][0];
        ch1 = sC[bsub][1];
        ch2 = sC[bsub][2];
        ch3 = sC[bsub][3];
    }

    float c0 = fmaf(Fe0, ch0, Ce0);
    float c1 = fmaf(Fe1, ch1, Ce1);
    float c2 = fmaf(Fe2, ch2, Ce2);
    float c3 = fmaf(Fe3, ch3, Ce3);

    // ---- pass 2: register recurrence, emit h ----
    float4* __restrict__ out4 = (float4*)out;
    float h0 = 0.f, h1 = 0.f, h2 = 0.f, h3 = 0.f;

#pragma unroll
    for (int it = 0; it < CHUNK; ++it) {
        float2 oA = __half22float2(OcA[it]);
        float2 oB = __half22float2(OcB[it]);

        c0 = fmaf(Fc[it][0], c0, Gc[it][0]);
        c1 = fmaf(Fc[it][1], c1, Gc[it][1]);
        c2 = fmaf(Fc[it][2], c2, Gc[it][2]);
        c3 = fmaf(Fc[it][3], c3, Gc[it][3]);

        h0 = oA.x * tanh_p54(c0);
        h1 = oA.y * tanh_p54(c1);
        h2 = oB.x * tanh_p54(c2);
        h3 = oB.y * tanh_p54(c3);

        __stcs(&out4[(t0 + it) * BATCH + b], make_float4(h0, h1, h2, h3));
    }

    // final state from half 1, chunk 15, it=3 (t = 127)
    if (half == 1 && chunk == 15) {
        out4[T_STEPS * BATCH + b]         = make_float4(h0, h1, h2, h3); // hx
        out4[T_STEPS * BATCH + BATCH + b] = make_float4(c0, c1, c2, c3); // cx
    }
}

extern "C" void kernel_launch(void* const* d_in, const int* in_sizes, int n_in,
                              void* d_out, int out_size) {
    (void)in_sizes; (void)n_in; (void)out_size;
    const float* inp   = (const float*)d_in[0];
    const float* prm_f = (const float*)d_in[1];
    const float* prm_i = (const float*)d_in[2];
    const float* prm_g = (const float*)d_in[3];
    const float* prm_o = (const float*)d_in[4];
    float* out = (float*)d_out;

    // 4096 warps: block = 2 warps (2 halves of one b-pair) -> 2048 blocks
    qlstm_kernel<<<2048, 64>>>(inp, prm_f, prm_i, prm_g, prm_o, out);
}